// round 17
// baseline (speedup 1.0000x reference)
#include <cuda_runtime.h>
#include <cuda_bf16.h>
#include <cuda_fp16.h>
#include <math.h>
#include <stdint.h>

#define N_SEQ 4096
#define N_HEADS 16
#define DIM_HEAD 64
#define DIM 1024
#define CMAX 18.5f

// ---------------- scratch (device globals; no allocation allowed) ----------
// q/k after rope+l2norm+qk_scale (+0.125*log2e folded into q), packed fp16
// pair words, FRAGMENT-PERMUTED within each 32-word row: original word w
// (dims 2w,2w+1) lives at position (w>>3)*8 + (w&3)*2 + ((w>>2)&1), so the
// B-fragment pair (w, w+4) is adjacent (one LDS.64 / LDG.64). [h][n][32w].
__device__ uint32_t g_qf[N_HEADS * N_SEQ * 32];
__device__ uint32_t g_kf[N_HEADS * N_SEQ * 32];
// v as fp16 key-pair words, PV-fragment paired:
// g_vp2[h][tile][pair][d] = { packh2(V[2kp][d],V[2kp+1][d]),
//                             packh2(V[2kp+8][d],V[2kp+9][d]) }
// where kp = tile*32 + (pair>>2)*8 + (pair&3); pair = k2*4+c; d = 0..63.
__device__ uint2 g_vp2[N_HEADS * 64 * 16 * 64];
__device__ float g_wr [DIM * DIM];                   // w_out, tf32-rna, natural [j][i]
__device__ float g_attn[N_SEQ * DIM];                // attention out, tf32-rna, [n][dim]
__device__ float g_cos[N_SEQ * 32];
__device__ float g_sin[N_SEQ * 32];

// ---------------- helpers ---------------------------------------------------
__device__ __forceinline__ uint32_t smem_u32(const void* p) {
    uint32_t a;
    asm("{ .reg .u64 t; cvta.to.shared.u64 t, %1; cvt.u32.u64 %0, t; }" : "=r"(a) : "l"(p));
    return a;
}
__device__ __forceinline__ float tf32_rna(float x) {
    uint32_t r;
    asm("cvt.rna.tf32.f32 %0, %1;" : "=r"(r) : "f"(x));
    return __uint_as_float(r);
}
__device__ __forceinline__ float ex2(float x) {
    float r;
    asm("ex2.approx.ftz.f32 %0, %1;" : "=f"(r) : "f"(x));
    return r;
}
__device__ __forceinline__ uint32_t packh2(float a, float b) {
    __half2 t = __floats2half2_rn(a, b);   // a -> low half (lower index)
    return *(uint32_t*)&t;
}
// tf32 m16n8k8 (projection)
__device__ __forceinline__ void mma8(float* c,
    uint32_t a0, uint32_t a1, uint32_t a2, uint32_t a3,
    uint32_t b0, uint32_t b1)
{
    asm volatile(
        "mma.sync.aligned.m16n8k8.row.col.f32.tf32.tf32.f32 "
        "{%0,%1,%2,%3}, {%4,%5,%6,%7}, {%8,%9}, {%0,%1,%2,%3};"
        : "+f"(c[0]), "+f"(c[1]), "+f"(c[2]), "+f"(c[3])
        : "r"(a0), "r"(a1), "r"(a2), "r"(a3), "r"(b0), "r"(b1));
}
// fp16 m16n8k16 (S and PV), fp32 accumulate
__device__ __forceinline__ void mma16h(float* c,
    uint32_t a0, uint32_t a1, uint32_t a2, uint32_t a3,
    uint32_t b0, uint32_t b1)
{
    asm volatile(
        "mma.sync.aligned.m16n8k16.row.col.f32.f16.f16.f32 "
        "{%0,%1,%2,%3}, {%4,%5,%6,%7}, {%8,%9}, {%0,%1,%2,%3};"
        : "+f"(c[0]), "+f"(c[1]), "+f"(c[2]), "+f"(c[3])
        : "r"(a0), "r"(a1), "r"(a2), "r"(a3), "r"(b0), "r"(b1));
}
__device__ __forceinline__ void cp16(uint32_t dst, const void* src) {
    asm volatile("cp.async.cg.shared.global [%0], [%1], 16;" :: "r"(dst), "l"(src));
}
#define CP_COMMIT() asm volatile("cp.async.commit_group;" ::: "memory")
#define CP_WAIT1()  asm volatile("cp.async.wait_group 1;" ::: "memory")
#define CP_WAIT0()  asm volatile("cp.async.wait_group 0;" ::: "memory")

// ---------------------------------------------------------------------------
// Kernel 0: RoPE tables (double sincos of the fp32-rounded angle)
// ---------------------------------------------------------------------------
__global__ void rope_table_kernel() {
    int idx = blockIdx.x * blockDim.x + threadIdx.x;
    if (idx >= N_SEQ * 32) return;
    int n = idx >> 5, l = idx & 31;
    float invf = (float)exp(-((double)l / 32.0) * log(10000.0));
    float ang = (float)n * invf;
    double s, c;
    sincos((double)ang, &s, &c);
    g_cos[idx] = (float)c;
    g_sin[idx] = (float)s;
}

// ---------------------------------------------------------------------------
// Kernel 1: prep q/k: RoPE + l2norm + qk_scale (+0.125*log2e into q),
// packed fp16, fragment-permuted word order. One warp per (token, head).
// ---------------------------------------------------------------------------
__global__ __launch_bounds__(256) void prep_qk_kernel(
    const float* __restrict__ q, const float* __restrict__ k,
    const float* __restrict__ qk_scale)
{
    int wi = blockIdx.x * 8 + (threadIdx.x >> 5);   // 0..65535
    int l = threadIdx.x & 31;
    int h = wi & 15;
    int n = wi >> 4;
    const float* src = (blockIdx.y == 0) ? q : k;
    uint32_t* dst = (blockIdx.y == 0) ? g_qf : g_kf;
    float fold = (blockIdx.y == 0) ? (0.125f * 1.4426950408889634f) : 1.0f;

    float2 x = ((const float2*)(src + (size_t)n * DIM + h * DIM_HEAD))[l];
    float2 sc = ((const float2*)qk_scale)[l];
    float c = g_cos[n * 32 + l], s = g_sin[n * 32 + l];
    float orr = x.x * c - x.y * s;
    float oii = x.x * s + x.y * c;
    float sq = orr * orr + oii * oii;
    #pragma unroll
    for (int m = 16; m; m >>= 1) sq += __shfl_xor_sync(0xffffffffu, sq, m);
    float f = fold / fmaxf(sqrtf(sq), 1e-12f);
    int wperm = (l >> 3) * 8 + (l & 3) * 2 + ((l >> 2) & 1);
    dst[((size_t)h * N_SEQ + n) * 32 + wperm] = packh2(orr * f * sc.x, oii * f * sc.y);
}

// ---------------------------------------------------------------------------
// Kernel 2a: v -> PV-fragment-paired fp16 layout g_vp2.
// Thread: one (h, tile, pair, 4-dim chunk); reads 4 key rows, writes 4 uint2.
// ---------------------------------------------------------------------------
__global__ __launch_bounds__(256) void vpair_kernel(const float* __restrict__ v) {
    int id = blockIdx.x * 256 + threadIdx.x;       // 0 .. 262143
    int chunk = id & 15;
    int pair  = (id >> 4) & 15;
    int t     = (id >> 8) & 63;
    int h     = id >> 14;
    int kp = t * 32 + ((pair >> 2) << 3) + (pair & 3);
    int key0 = 2 * kp;                              // keys key0, +1, +8, +9
    const float* vp = v + h * 64 + chunk * 4;
    float4 a0 = *(const float4*)(vp + (size_t)key0 * DIM);
    float4 a1 = *(const float4*)(vp + (size_t)(key0 + 1) * DIM);
    float4 b0 = *(const float4*)(vp + (size_t)(key0 + 8) * DIM);
    float4 b1 = *(const float4*)(vp + (size_t)(key0 + 9) * DIM);
    uint2* dst = g_vp2 + (((size_t)(h * 64 + t) * 16 + pair) * 64 + chunk * 4);
    dst[0] = make_uint2(packh2(a0.x, a1.x), packh2(b0.x, b1.x));
    dst[1] = make_uint2(packh2(a0.y, a1.y), packh2(b0.y, b1.y));
    dst[2] = make_uint2(packh2(a0.z, a1.z), packh2(b0.z, b1.z));
    dst[3] = make_uint2(packh2(a0.w, a1.w), packh2(b0.w, b1.w));
}

// ---------------------------------------------------------------------------
// Kernel 2b: elementwise rna rounding of w_out (tf32 operand for proj)
// ---------------------------------------------------------------------------
__global__ __launch_bounds__(256) void wround_kernel(const float* __restrict__ w) {
    int i = blockIdx.x * 256 + threadIdx.x;
    float4 x = ((const float4*)w)[i];
    ((float4*)g_wr)[i] = make_float4(tf32_rna(x.x), tf32_rna(x.y), tf32_rna(x.z), tf32_rna(x.w));
}

// ---------------------------------------------------------------------------
// Kernel 3: flash attention, all-fp16 MMA, LDS.64 fragment loads.
// CTA = 128 q-rows x 1 head; 8 warps x 16 rows; 64 KV tiles, double-buffered.
// S: fp16 m16n8k16, K pairs via LDS.64 (stride 20 uint2: banks 4r+c, clean).
// PV: fp16 m16n8k16, V pairs via LDS.64 (stride 68 uint2: banks 4c+r, clean).
// Fixed-max softmax (CMAX), O fp32 across tiles. 2 CTAs/SM.
// SMEM per buffer: K 64x160B (10240) + Vp 16x544B (8704) = 18944B; x2 buf.
// ---------------------------------------------------------------------------
#define V_OFF 10240
#define KV_STR_B 18944
#define ATTN_SMEM_BYTES (2 * KV_STR_B)

__device__ __forceinline__ void issue_kv(uint32_t base, int h, int k0, int tid)
{
    #pragma unroll
    for (int j = 0; j < 2; j++) {
        int id = tid + j * 256;       // 0..511
        int row = id >> 3;            // 0..63
        int ch = id & 7;              // 16B chunk
        cp16(base + (uint32_t)(row * 160 + ch * 16),
             g_kf + ((size_t)h * N_SEQ + k0 + row) * 32 + ch * 4);
    }
    int t = k0 >> 6;
    #pragma unroll
    for (int j = 0; j < 2; j++) {
        int id = tid + j * 256;       // 0..511
        int row = id >> 5;            // pair 0..15
        int ch = id & 31;             // 16B chunk (2 uint2)
        cp16(base + (uint32_t)(V_OFF + row * 544 + ch * 16),
             (const char*)g_vp2 + (((size_t)(h * 64 + t) * 16 + row) * 64 + ch * 2) * 8);
    }
}

__global__ __launch_bounds__(256, 2) void attn_kernel()
{
    extern __shared__ char smb[];
    uint32_t kvu0 = smem_u32(smb);

    int tid = threadIdx.x;
    int warp = tid >> 5, lane = tid & 31;
    int r = lane >> 2, c = lane & 3;
    int h = blockIdx.y, m0 = blockIdx.x * 128;

    issue_kv(kvu0, h, 0, tid);             CP_COMMIT();
    issue_kv(kvu0 + KV_STR_B, h, 64, tid); CP_COMMIT();

    // Q fragments, tile-invariant (permuted layout -> LDG.64 pairs)
    uint32_t qf[4][4];
    {
        const uint2* qp2 = (const uint2*)(g_qf + ((size_t)h * N_SEQ + m0 + warp * 16 + r) * 32);
        #pragma unroll
        for (int ks = 0; ks < 4; ks++) {
            uint2 u = qp2[ks * 4 + c];
            uint2 w = qp2[128 + ks * 4 + c];
            qf[ks][0] = u.x; qf[ks][2] = u.y;
            qf[ks][1] = w.x; qf[ks][3] = w.y;
        }
    }

    float s[8][4], o[8][4];
    float lsum0 = 0.0f, lsum1 = 0.0f;
    #pragma unroll
    for (int nf = 0; nf < 8; nf++)
        #pragma unroll
        for (int e = 0; e < 4; e++) o[nf][e] = 0.0f;

    for (int t = 0; t < 64; t++) {
        if (t == 63) { CP_WAIT0(); } else { CP_WAIT1(); }
        __syncthreads();
        const uint2* K2 = (const uint2*)(smb + (t & 1) * KV_STR_B);
        const uint2* V2 = (const uint2*)(smb + (t & 1) * KV_STR_B + V_OFF);

        #pragma unroll
        for (int nf = 0; nf < 8; nf++)
            #pragma unroll
            for (int e = 0; e < 4; e++) s[nf][e] = 0.0f;

        // ---- S = Q K^T, fp16 k16; K fragment pairs via LDS.64 ----
        #pragma unroll
        for (int nf = 0; nf < 8; nf++) {
            const uint2* kb = K2 + (nf * 8 + r) * 20 + c;
            #pragma unroll
            for (int ks = 0; ks < 4; ks++) {
                uint2 b = kb[ks * 4];
                mma16h(s[nf], qf[ks][0], qf[ks][1], qf[ks][2], qf[ks][3], b.x, b.y);
            }
        }

        // ---- softmax numerators (log2 units, fixed shift) ----
        #pragma unroll
        for (int nf = 0; nf < 8; nf++) {
            s[nf][0] = ex2(s[nf][0] - CMAX);
            s[nf][1] = ex2(s[nf][1] - CMAX);
            s[nf][2] = ex2(s[nf][2] - CMAX);
            s[nf][3] = ex2(s[nf][3] - CMAX);
            lsum0 += s[nf][0] + s[nf][1];
            lsum1 += s[nf][2] + s[nf][3];
        }

        // ---- O += P V (fp16 k16): direct C->A packs; V pairs via LDS.64 ----
        #pragma unroll
        for (int k2 = 0; k2 < 4; k2++) {
            uint32_t a0 = packh2(s[2 * k2][0],     s[2 * k2][1]);
            uint32_t a1 = packh2(s[2 * k2][2],     s[2 * k2][3]);
            uint32_t a2 = packh2(s[2 * k2 + 1][0], s[2 * k2 + 1][1]);
            uint32_t a3 = packh2(s[2 * k2 + 1][2], s[2 * k2 + 1][3]);
            const uint2* vb = V2 + (k2 * 4 + c) * 68 + r;
            #pragma unroll
            for (int nf = 0; nf < 8; nf++) {
                uint2 b = vb[nf * 8];
                mma16h(o[nf], a0, a1, a2, a3, b.x, b.y);
            }
        }

        __syncthreads();
        if (t + 2 < 64) {
            issue_kv(kvu0 + (uint32_t)(t & 1) * KV_STR_B, h, (t + 2) * 64, tid);
            CP_COMMIT();
        }
    }

    // ---- epilogue: quad row sums, normalize, rna, store ----
    lsum0 += __shfl_xor_sync(0xffffffffu, lsum0, 1);
    lsum0 += __shfl_xor_sync(0xffffffffu, lsum0, 2);
    lsum1 += __shfl_xor_sync(0xffffffffu, lsum1, 1);
    lsum1 += __shfl_xor_sync(0xffffffffu, lsum1, 2);
    float inv0 = 1.0f / lsum0, inv1 = 1.0f / lsum1;
    int row0 = m0 + warp * 16 + r;
    #pragma unroll
    for (int nf = 0; nf < 8; nf++) {
        int col = h * DIM_HEAD + nf * 8 + 2 * c;
        float2 x0 = make_float2(tf32_rna(o[nf][0] * inv0), tf32_rna(o[nf][1] * inv0));
        float2 x1 = make_float2(tf32_rna(o[nf][2] * inv1), tf32_rna(o[nf][3] * inv1));
        *(float2*)&g_attn[(size_t)row0 * DIM + col] = x0;
        *(float2*)&g_attn[(size_t)(row0 + 8) * DIM + col] = x1;
    }
}

// ---------------------------------------------------------------------------
// Kernel 4: projection GEMM on mma.sync tf32 (unchanged, validated R5/R8).
// out[n][j] = sum_i attn[n][i] * w[j][i] + b[j]. CTA 128x128, warps 4x2.
// ---------------------------------------------------------------------------
#define PROJ_STRF 17408
#define PROJ_SMEM_BYTES (2 * PROJ_STRF * 4)

__device__ __forceinline__ void issue_proj(uint32_t base, int m0, int j0, int k0, int tid)
{
    #pragma unroll
    for (int j = 0; j < 8; j++) {
        int id = tid + j * 256;
        int row = id >> 4;
        int c4 = (id & 15) * 4;
        cp16(base + (uint32_t)(row * 68 + c4) * 4u,
             g_attn + (size_t)(m0 + row) * DIM + k0 + c4);
        cp16(base + (uint32_t)(8704 + row * 68 + c4) * 4u,
             g_wr + (size_t)(j0 + row) * DIM + k0 + c4);
    }
}

__global__ __launch_bounds__(256) void proj_kernel(
    const float* __restrict__ b_out, float* __restrict__ out)
{
    extern __shared__ float sm[];
    uint32_t smu = smem_u32(sm);
    int tid = threadIdx.x;
    int warp = tid >> 5, lane = tid & 31;
    int r = lane >> 2, c = lane & 3;
    int mw = warp >> 1, nw = warp & 1;
    int m0 = blockIdx.x * 128, j0 = blockIdx.y * 128;

    float acc[2][8][4];
    #pragma unroll
    for (int mf = 0; mf < 2; mf++)
        #pragma unroll
        for (int nf = 0; nf < 8; nf++)
            #pragma unroll
            for (int e = 0; e < 4; e++) acc[mf][nf][e] = 0.0f;

    issue_proj(smu, m0, j0, 0, tid);                    CP_COMMIT();
    issue_proj(smu + PROJ_STRF * 4u, m0, j0, 64, tid);  CP_COMMIT();

    for (int ch = 0; ch < 16; ch++) {
        if (ch == 15) { CP_WAIT0(); } else { CP_WAIT1(); }
        __syncthreads();
        float* As = sm + (ch & 1) * PROJ_STRF;
        float* Ws = As + 8704;

        #pragma unroll
        for (int ks = 0; ks < 8; ks++) {
            int k0 = ks * 8;
            uint32_t a[2][4];
            #pragma unroll
            for (int mf = 0; mf < 2; mf++) {
                const float* ab = &As[(mw * 32 + mf * 16 + r) * 68 + k0 + c];
                a[mf][0] = __float_as_uint(ab[0]);
                a[mf][1] = __float_as_uint(ab[8 * 68]);
                a[mf][2] = __float_as_uint(ab[4]);
                a[mf][3] = __float_as_uint(ab[8 * 68 + 4]);
            }
            #pragma unroll
            for (int nf = 0; nf < 8; nf++) {
                const float* wb = &Ws[(nw * 64 + nf * 8 + r) * 68 + k0 + c];
                uint32_t b0 = __float_as_uint(wb[0]);
                uint32_t b1 = __float_as_uint(wb[4]);
                mma8(acc[0][nf], a[0][0], a[0][1], a[0][2], a[0][3], b0, b1);
                mma8(acc[1][nf], a[1][0], a[1][1], a[1][2], a[1][3], b0, b1);
            }
        }

        __syncthreads();
        if (ch + 2 < 16) {
            issue_proj(smu + (uint32_t)(ch & 1) * PROJ_STRF * 4u, m0, j0, (ch + 2) * 64, tid);
            CP_COMMIT();
        }
    }

    #pragma unroll
    for (int mf = 0; mf < 2; mf++) {
        int row = m0 + mw * 32 + mf * 16 + r;
        #pragma unroll
        for (int nf = 0; nf < 8; nf++) {
            int col = j0 + nw * 64 + nf * 8 + 2 * c;
            float2 bb = *(const float2*)&b_out[col];
            *(float2*)&out[(size_t)row * DIM + col] =
                make_float2(acc[mf][nf][0] + bb.x, acc[mf][nf][1] + bb.y);
            *(float2*)&out[(size_t)(row + 8) * DIM + col] =
                make_float2(acc[mf][nf][2] + bb.x, acc[mf][nf][3] + bb.y);
        }
    }
}

// ---------------------------------------------------------------------------
extern "C" void kernel_launch(void* const* d_in, const int* in_sizes, int n_in,
                              void* d_out, int out_size)
{
    const float* q        = (const float*)d_in[0];
    const float* k        = (const float*)d_in[1];
    const float* v        = (const float*)d_in[2];
    const float* qk_scale = (const float*)d_in[3];
    const float* w_out    = (const float*)d_in[4];
    const float* b_out    = (const float*)d_in[5];
    float* out = (float*)d_out;

    cudaFuncSetAttribute(attn_kernel,
                         cudaFuncAttributeMaxDynamicSharedMemorySize, ATTN_SMEM_BYTES);
    cudaFuncSetAttribute(proj_kernel,
                         cudaFuncAttributeMaxDynamicSharedMemorySize, PROJ_SMEM_BYTES);

    rope_table_kernel<<<(N_SEQ * 32 + 255) / 256, 256>>>();
    prep_qk_kernel<<<dim3(8192, 2), 256>>>(q, k, qk_scale);
    vpair_kernel<<<1024, 256>>>(v);
    wround_kernel<<<(DIM * DIM / 4) / 256, 256>>>(w_out);
    attn_kernel<<<dim3(N_SEQ / 128, N_HEADS), 256, ATTN_SMEM_BYTES>>>();
    proj_kernel<<<dim3(N_SEQ / 128, DIM / 128), 256, PROJ_SMEM_BYTES>>>(b_out, out);
}